// round 16
// baseline (speedup 1.0000x reference)
#include <cuda_runtime.h>
#include <cuda_bf16.h>
#include <math_constants.h>
#include <cstdint>

// Problem dims (fixed): B=64, T=512, D=256, C=1024, H=1
#define N_TOK 32768
#define DIM   256
#define NCODE 1024

#define DECAY 0.99f
#define ONE_M_DECAY 0.01f
#define EPS 1e-5f

// Output packing (tuple flattened, all float32):
#define OFF_Q    0
#define OFF_IND  8388608
#define OFF_NORM 8421376
#define OFF_CS   8683520

#define NCHUNK 16   // code chunks of 64
#define SORT_BLKS 128
#define TOK_PER_BLK 256

// ---------------- scratch (no cudaMalloc allowed) ----------------
__device__ float g_esum[NCODE * DIM];
__device__ float g_enorm[NCODE];
__device__ float g_cssum;
__device__ int   g_idx[N_TOK];
__device__ float g_pbest[NCHUNK * N_TOK];
__device__ int   g_pidx[NCHUNK * N_TOK];
__device__ int   g_hist[SORT_BLKS][NCODE];
__device__ int   g_base[SORT_BLKS][NCODE];
__device__ int   g_off[NCODE];
__device__ int   g_count[NCODE];
__device__ int   g_sorted[N_TOK];

// ---------------- mma helpers (baseline PTX, sm_80+) ----------------
__device__ __forceinline__ void ldsm_x4(uint32_t* r, uint32_t addr) {
    asm volatile("ldmatrix.sync.aligned.m8n8.x4.shared.b16 {%0,%1,%2,%3}, [%4];"
        : "=r"(r[0]), "=r"(r[1]), "=r"(r[2]), "=r"(r[3]) : "r"(addr));
}
__device__ __forceinline__ void ldsm_x2(uint32_t* r, uint32_t addr) {
    asm volatile("ldmatrix.sync.aligned.m8n8.x2.shared.b16 {%0,%1}, [%2];"
        : "=r"(r[0]), "=r"(r[1]) : "r"(addr));
}
__device__ __forceinline__ void mma_bf16(float* d, const uint32_t* a, const uint32_t* b) {
    asm volatile("mma.sync.aligned.m16n8k16.row.col.f32.bf16.bf16.f32 "
        "{%0,%1,%2,%3}, {%4,%5,%6,%7}, {%8,%9}, {%0,%1,%2,%3};"
        : "+f"(d[0]), "+f"(d[1]), "+f"(d[2]), "+f"(d[3])
        : "r"(a[0]), "r"(a[1]), "r"(a[2]), "r"(a[3]), "r"(b[0]), "r"(b[1]));
}

// split fp32 -> bf16 hi + bf16 lo
__device__ __forceinline__ void bsplit(float v, unsigned short& h, unsigned short& l) {
    __nv_bfloat16 hb = __float2bfloat16(v);
    h = __bfloat16_as_ushort(hb);
    l = __bfloat16_as_ushort(__float2bfloat16(v - __bfloat162float(hb)));
}

// ---------------- smem layout (dynamic) ----------------
#define ROWB 80            // 40 bf16 row stride in bytes
#define A_HI 0
#define A_LO 10240
#define B_HI 20480
#define B_LO 25600
#define BUFB 30720
#define DSMEM_BYTES (2 * BUFB)

// ---------------- kernel 1: ||e_c||^2 + sum(cluster_size) ----------------
__global__ void k_enorm(const float* __restrict__ embed,
                        const float* __restrict__ cluster_size) {
    if (blockIdx.x == 256) {
        __shared__ float red[128];
        int t = threadIdx.x;
        float s = 0.0f;
#pragma unroll
        for (int i = 0; i < 8; ++i) s += cluster_size[t + 128 * i];
        red[t] = s;
        __syncthreads();
#pragma unroll
        for (int o = 64; o > 0; o >>= 1) {
            if (t < o) red[t] += red[t + o];
            __syncthreads();
        }
        if (t == 0) g_cssum = red[0];
        return;
    }
    int w = threadIdx.x >> 5;
    int l = threadIdx.x & 31;
    int code = blockIdx.x * 4 + w;
    const float* row = embed + (size_t)code * DIM;
    float s = 0.0f;
#pragma unroll
    for (int i = 0; i < 8; ++i) {
        float v = row[l + 32 * i];
        s = fmaf(v, v, s);
    }
#pragma unroll
    for (int off = 16; off > 0; off >>= 1)
        s += __shfl_down_sync(0xffffffffu, s, off);
    if (l == 0) g_enorm[code] = s;
}

// ---------------- kernel 2: bf16x3 mma.sync GEMM + partial argmax ----------------
// R11-exact (measured 160us, tensor 52.5%). grid (256, 16), 256 threads = 8 warps.
__global__ void __launch_bounds__(256, 2)
k_gemm_mma(const float* __restrict__ x, const float* __restrict__ embed) {
    extern __shared__ char smem[];
    uint32_t sb;
    asm("{ .reg .u64 t; cvta.to.shared.u64 t, %1; cvt.u32.u64 %0, t; }"
        : "=r"(sb) : "l"(smem));

    const int tid = threadIdx.x;
    const int wid = tid >> 5;
    const int lane = tid & 31;
    const int wm = wid & 3;      // token strip (32)
    const int wn = wid >> 2;     // code strip (32)
    const int blockTok = blockIdx.x * 128;
    const int cc = blockIdx.y;
    const int code0 = cc * 64;

    float acc[2][4][4];
#pragma unroll
    for (int t = 0; t < 2; ++t)
#pragma unroll
        for (int j = 0; j < 4; ++j)
#pragma unroll
            for (int r = 0; r < 4; ++r) acc[t][j][r] = 0.0f;

    const uint32_t arow = (uint32_t)((wm * 32 + (lane & 15)) * ROWB + (lane >> 4) * 16);
    const uint32_t brow = (uint32_t)((wn * 32 + (lane & 7)) * ROWB + ((lane >> 3) & 1) * 16);

    float regA[16];
    float regB[8];

    // ---- prologue: load stage 0 ----
#pragma unroll
    for (int i = 0; i < 4; ++i) {
        int s_ = tid + i * 256;
        int row = s_ >> 3, ch = s_ & 7;
        *(float4*)(regA + i * 4) = *(const float4*)(x + (size_t)(blockTok + row) * DIM + ch * 4);
    }
#pragma unroll
    for (int i = 0; i < 2; ++i) {
        int s_ = tid + i * 256;
        int row = s_ >> 3, ch = s_ & 7;
        *(float4*)(regB + i * 4) = *(const float4*)(embed + (size_t)(code0 + row) * DIM + ch * 4);
    }

    for (int s = 0; s < 8; ++s) {
        const int b = s & 1;
        const char* bufw = smem + (b * BUFB);
        // store staged regs (stage s) into buffer b
#pragma unroll
        for (int i = 0; i < 4; ++i) {
            int s_ = tid + i * 256;
            int row = s_ >> 3, ch = s_ & 7;
            unsigned short h0, l0, h1, l1, h2, l2, h3, l3;
            bsplit(regA[i * 4 + 0], h0, l0);
            bsplit(regA[i * 4 + 1], h1, l1);
            bsplit(regA[i * 4 + 2], h2, l2);
            bsplit(regA[i * 4 + 3], h3, l3);
            uint2 hv = make_uint2((uint32_t)h0 | ((uint32_t)h1 << 16),
                                  (uint32_t)h2 | ((uint32_t)h3 << 16));
            uint2 lv = make_uint2((uint32_t)l0 | ((uint32_t)l1 << 16),
                                  (uint32_t)l2 | ((uint32_t)l3 << 16));
            *(uint2*)(bufw + A_HI + row * ROWB + ch * 8) = hv;
            *(uint2*)(bufw + A_LO + row * ROWB + ch * 8) = lv;
        }
#pragma unroll
        for (int i = 0; i < 2; ++i) {
            int s_ = tid + i * 256;
            int row = s_ >> 3, ch = s_ & 7;
            unsigned short h0, l0, h1, l1, h2, l2, h3, l3;
            bsplit(regB[i * 4 + 0], h0, l0);
            bsplit(regB[i * 4 + 1], h1, l1);
            bsplit(regB[i * 4 + 2], h2, l2);
            bsplit(regB[i * 4 + 3], h3, l3);
            uint2 hv = make_uint2((uint32_t)h0 | ((uint32_t)h1 << 16),
                                  (uint32_t)h2 | ((uint32_t)h3 << 16));
            uint2 lv = make_uint2((uint32_t)l0 | ((uint32_t)l1 << 16),
                                  (uint32_t)l2 | ((uint32_t)l3 << 16));
            *(uint2*)(bufw + B_HI + row * ROWB + ch * 8) = hv;
            *(uint2*)(bufw + B_LO + row * ROWB + ch * 8) = lv;
        }
        __syncthreads();

        // prefetch stage s+1 into regs (overlaps with mma below)
        if (s < 7) {
            const int kg = (s + 1) * 32;
#pragma unroll
            for (int i = 0; i < 4; ++i) {
                int s_ = tid + i * 256;
                int row = s_ >> 3, ch = s_ & 7;
                *(float4*)(regA + i * 4) = *(const float4*)(x + (size_t)(blockTok + row) * DIM + kg + ch * 4);
            }
#pragma unroll
            for (int i = 0; i < 2; ++i) {
                int s_ = tid + i * 256;
                int row = s_ >> 3, ch = s_ & 7;
                *(float4*)(regB + i * 4) = *(const float4*)(embed + (size_t)(code0 + row) * DIM + kg + ch * 4);
            }
        }

        // ---- compute on buffer b: 2 k16 steps, 3 split-products each ----
        const uint32_t base = sb + b * BUFB;
#pragma unroll
        for (int ks = 0; ks < 2; ++ks) {
            const uint32_t k0b = ks * 32;  // 16 bf16 = 32 bytes
            uint32_t af[2][4], bh[4][2], bl[4][2];
#pragma unroll
            for (int j = 0; j < 4; ++j) {
                ldsm_x2(bh[j], base + B_HI + brow + j * 8 * ROWB + k0b);
                ldsm_x2(bl[j], base + B_LO + brow + j * 8 * ROWB + k0b);
            }
#pragma unroll
            for (int t = 0; t < 2; ++t)
                ldsm_x4(af[t], base + A_HI + arow + t * 16 * ROWB + k0b);
#pragma unroll
            for (int t = 0; t < 2; ++t)
#pragma unroll
                for (int j = 0; j < 4; ++j) mma_bf16(acc[t][j], af[t], bh[j]);
#pragma unroll
            for (int t = 0; t < 2; ++t)
#pragma unroll
                for (int j = 0; j < 4; ++j) mma_bf16(acc[t][j], af[t], bl[j]);
#pragma unroll
            for (int t = 0; t < 2; ++t)
                ldsm_x4(af[t], base + A_LO + arow + t * 16 * ROWB + k0b);
#pragma unroll
            for (int t = 0; t < 2; ++t)
#pragma unroll
                for (int j = 0; j < 4; ++j) mma_bf16(acc[t][j], af[t], bh[j]);
        }
        // no end-of-stage sync needed (store(s+2) gated by sync(s+1))
    }

    // ---- epilogue: score + argmax ----
    const int g = lane >> 2;       // row within 8
    const int tg = lane & 3;       // col pair selector
    float best[4];
    int bidx[4];
#pragma unroll
    for (int r = 0; r < 4; ++r) { best[r] = -CUDART_INF_F; bidx[r] = 0x7fffffff; }

#pragma unroll
    for (int t = 0; t < 2; ++t) {
#pragma unroll
        for (int j = 0; j < 4; ++j) {
            int c0 = code0 + wn * 32 + j * 8 + tg * 2;
            float e0 = __ldg(&g_enorm[c0]);
            float e1 = __ldg(&g_enorm[c0 + 1]);
            float s00 = fmaf(2.0f, acc[t][j][0], -e0);
            float s01 = fmaf(2.0f, acc[t][j][1], -e1);
            float s10 = fmaf(2.0f, acc[t][j][2], -e0);
            float s11 = fmaf(2.0f, acc[t][j][3], -e1);
            int r0 = t * 2, r1 = t * 2 + 1;
            if (s00 > best[r0]) { best[r0] = s00; bidx[r0] = c0; }
            if (s01 > best[r0]) { best[r0] = s01; bidx[r0] = c0 + 1; }
            if (s10 > best[r1]) { best[r1] = s10; bidx[r1] = c0; }
            if (s11 > best[r1]) { best[r1] = s11; bidx[r1] = c0 + 1; }
        }
    }
#pragma unroll
    for (int r = 0; r < 4; ++r) {
#pragma unroll
        for (int off = 1; off < 4; off <<= 1) {
            float os = __shfl_xor_sync(0xffffffffu, best[r], off);
            int   oi = __shfl_xor_sync(0xffffffffu, bidx[r], off);
            if (os > best[r] || (os == best[r] && oi < bidx[r])) { best[r] = os; bidx[r] = oi; }
        }
    }

    __syncthreads();  // buffers done; reuse smem as reduce scratch
    float* red_s = (float*)smem;               // [128][2]
    int*   red_i = (int*)(smem + 1024);        // [128][2]
    if (tg == 0) {
#pragma unroll
        for (int r = 0; r < 4; ++r) {
            int t = r >> 1, rh = r & 1;
            int lrow = wm * 32 + t * 16 + rh * 8 + g;
            red_s[lrow * 2 + wn] = best[r];
            red_i[lrow * 2 + wn] = bidx[r];
        }
    }
    __syncthreads();
    if (tid < 128) {
        float s0 = red_s[tid * 2], s1 = red_s[tid * 2 + 1];
        int i0 = red_i[tid * 2], i1 = red_i[tid * 2 + 1];
        float bs = s0; int bb = i0;
        if (s1 > s0) { bs = s1; bb = i1; }   // strip 0 has lower codes: tie keeps 0
        int tok = blockTok + tid;
        g_pbest[cc * N_TOK + tok] = bs;
        g_pidx[cc * N_TOK + tok] = bb;
    }
}

// ---------------- kernel 3: fused cross-chunk argmax + gather quantize ----------------
__global__ void k_argmax_quant(const float* __restrict__ embed,
                               float* __restrict__ out_ind,
                               float* __restrict__ out_q) {
    int token = blockIdx.x * 8 + (threadIdx.x >> 5);
    int lane = threadIdx.x & 31;

    float bs = -CUDART_INF_F;
    int bi = 0x7fffffff;
    if (lane < NCHUNK) {
        bs = g_pbest[lane * N_TOK + token];
        bi = g_pidx[lane * N_TOK + token];
    }
#pragma unroll
    for (int off = 8; off > 0; off >>= 1) {
        float os = __shfl_down_sync(0xffffffffu, bs, off, 16);
        int   oi = __shfl_down_sync(0xffffffffu, bi, off, 16);
        if (os > bs || (os == bs && oi < bi)) { bs = os; bi = oi; }
    }
    bi = __shfl_sync(0xffffffffu, bi, 0);
    if (lane == 0) {
        g_idx[token] = bi;
        out_ind[token] = (float)bi;
    }
    const float4* er = (const float4*)(embed + (size_t)bi * DIM);
    float4* qw = (float4*)(out_q + (size_t)token * DIM);
    qw[lane] = er[lane];
    qw[lane + 32] = er[lane + 32];
}

// ---------------- kernel 4a: per-block code histogram ----------------
__global__ __launch_bounds__(256)
void k_hist() {
    __shared__ int hist[NCODE];
    const int s = blockIdx.x;
    const int tid = threadIdx.x;
    const int lane = tid & 31;
#pragma unroll
    for (int i = tid; i < NCODE; i += 256) hist[i] = 0;
    __syncthreads();
    int c = g_idx[s * TOK_PER_BLK + tid];
    unsigned m = __match_any_sync(0xffffffffu, c);
    if (lane == (__ffs(m) - 1)) atomicAdd(&hist[c], __popc(m));
    __syncthreads();
#pragma unroll
    for (int i = tid; i < NCODE; i += 256) g_hist[s][i] = hist[i];
}

// ---------------- kernel 4b: per-code scan (bases + global offsets) ----------------
__global__ __launch_bounds__(1024)
void k_scan() {
    const int c = threadIdx.x;
    int run = 0;
    for (int s = 0; s < SORT_BLKS; ++s) {
        int v = g_hist[s][c];
        g_base[s][c] = run;
        run += v;
    }
    g_count[c] = run;
    __shared__ int sc[NCODE];
    sc[c] = run;
    __syncthreads();
    // Hillis-Steele inclusive scan
    for (int off = 1; off < NCODE; off <<= 1) {
        int v = (c >= off) ? sc[c - off] : 0;
        __syncthreads();
        sc[c] += v;
        __syncthreads();
    }
    g_off[c] = sc[c] - run;   // exclusive
}

// ---------------- kernel 4c: stable scatter (tokens grouped by code) ----------------
__global__ __launch_bounds__(256)
void k_scatter() {
    __shared__ int whist[8][NCODE];   // 32KB
    const int s = blockIdx.x;
    const int tid = threadIdx.x;
    const int lane = tid & 31;
    const int w = tid >> 5;
#pragma unroll
    for (int i = tid; i < 8 * NCODE; i += 256) ((int*)whist)[i] = 0;
    __syncthreads();
    int t = s * TOK_PER_BLK + tid;
    int c = g_idx[t];
    unsigned m = __match_any_sync(0xffffffffu, c);
    int r = __popc(m & ((1u << lane) - 1u));
    if (lane == (__ffs(m) - 1)) whist[w][c] = __popc(m);
    __syncthreads();
    int wb = 0;
#pragma unroll
    for (int ww = 0; ww < 8; ++ww)
        if (ww < w) wb += whist[ww][c];
    int pos = g_off[c] + g_base[s][c] + wb + r;
    g_sorted[pos] = t;
}

// ---------------- kernel 4d: per-code gather accumulation ----------------
// One block per code; thread = dim. Tokens ascending within code (stable sort).
__global__ __launch_bounds__(256)
void k_accum2(const float* __restrict__ x) {
    const int c = blockIdx.x;
    const int tid = threadIdx.x;
    const int n = g_count[c];
    const int off = g_off[c];
    float acc = 0.0f;
    for (int j = 0; j < n; ++j) {
        int tok = g_sorted[off + j];
        acc += x[(size_t)tok * DIM + tid];
    }
    g_esum[(size_t)c * DIM + tid] = acc;
}

// ---------------- kernel 5: fused EMA + Laplace smoothing + embed_norm ----------------
__global__ void k_fin(const float* __restrict__ cluster_size,
                      const float* __restrict__ embed_avg,
                      float* __restrict__ out_cs,
                      float* __restrict__ out_norm) {
    const int c = blockIdx.x;
    const int tid = threadIdx.x;

    float cnt = (float)g_count[c];
    float csn = DECAY * cluster_size[c] + ONE_M_DECAY * cnt;
    float n = DECAY * g_cssum + ONE_M_DECAY * (float)N_TOK;
    float denom = (csn + EPS) / (n + (float)NCODE * EPS) * n;
    float inv = 1.0f / denom;

    size_t i = (size_t)c * DIM + tid;
    float ea = DECAY * embed_avg[i] + ONE_M_DECAY * g_esum[i];
    out_norm[i] = ea * inv;
    if (tid == 0) out_cs[c] = csn;
}

// ---------------- launch ----------------
extern "C" void kernel_launch(void* const* d_in, const int* in_sizes, int n_in,
                              void* d_out, int out_size) {
    const float* x = (const float*)d_in[0];
    const float* embed = (const float*)d_in[1];
    const float* embed_avg = (const float*)d_in[2];
    const float* cluster_size = (const float*)d_in[3];
    float* out = (float*)d_out;

    float* out_q    = out + OFF_Q;
    float* out_ind  = out + OFF_IND;
    float* out_norm = out + OFF_NORM;
    float* out_cs   = out + OFF_CS;

    cudaFuncSetAttribute(k_gemm_mma,
                         cudaFuncAttributeMaxDynamicSharedMemorySize,
                         DSMEM_BYTES);

    k_enorm<<<257, 128>>>(embed, cluster_size);
    dim3 g(N_TOK / 128, NCHUNK);
    k_gemm_mma<<<g, 256, DSMEM_BYTES>>>(x, embed);
    k_argmax_quant<<<N_TOK / 8, 256>>>(embed, out_ind, out_q);
    k_hist<<<SORT_BLKS, 256>>>();
    k_scan<<<1, 1024>>>();
    k_scatter<<<SORT_BLKS, 256>>>();
    k_accum2<<<NCODE, 256>>>(x);
    k_fin<<<NCODE, 256>>>(cluster_size, embed_avg, out_cs, out_norm);
}

// round 17
// speedup vs baseline: 1.2020x; 1.2020x over previous
#include <cuda_runtime.h>
#include <cuda_bf16.h>
#include <math_constants.h>
#include <cstdint>

// Problem dims (fixed): B=64, T=512, D=256, C=1024, H=1
#define N_TOK 32768
#define DIM   256
#define NCODE 1024

#define DECAY 0.99f
#define ONE_M_DECAY 0.01f
#define EPS 1e-5f

// Output packing (tuple flattened, all float32):
#define OFF_Q    0
#define OFF_IND  8388608
#define OFF_NORM 8421376
#define OFF_CS   8683520

#define NCHUNK 16   // code chunks of 64
#define NSEG 8
#define NCPB 8      // codes per accum block
#define SEG_TOK (N_TOK / NSEG)   // 4096

// ---------------- scratch (no cudaMalloc allowed) ----------------
__device__ float g_counts8[NSEG][NCODE];
__device__ float g_esum8[NSEG][NCODE * DIM];
__device__ float g_enorm[NCODE];
__device__ float g_cssum;
__device__ int   g_idx[N_TOK];
__device__ float g_pbest[NCHUNK * N_TOK];
__device__ int   g_pidx[NCHUNK * N_TOK];

// ---------------- mma helpers (baseline PTX, sm_80+) ----------------
__device__ __forceinline__ void ldsm_x4(uint32_t* r, uint32_t addr) {
    asm volatile("ldmatrix.sync.aligned.m8n8.x4.shared.b16 {%0,%1,%2,%3}, [%4];"
        : "=r"(r[0]), "=r"(r[1]), "=r"(r[2]), "=r"(r[3]) : "r"(addr));
}
__device__ __forceinline__ void mma_bf16(float* d, const uint32_t* a, const uint32_t* b) {
    asm volatile("mma.sync.aligned.m16n8k16.row.col.f32.bf16.bf16.f32 "
        "{%0,%1,%2,%3}, {%4,%5,%6,%7}, {%8,%9}, {%0,%1,%2,%3};"
        : "+f"(d[0]), "+f"(d[1]), "+f"(d[2]), "+f"(d[3])
        : "r"(a[0]), "r"(a[1]), "r"(a[2]), "r"(a[3]), "r"(b[0]), "r"(b[1]));
}

// split fp32 -> bf16 hi + bf16 lo
__device__ __forceinline__ void bsplit(float v, unsigned short& h, unsigned short& l) {
    __nv_bfloat16 hb = __float2bfloat16(v);
    h = __bfloat16_as_ushort(hb);
    l = __bfloat16_as_ushort(__float2bfloat16(v - __bfloat162float(hb)));
}

// ---------------- smem layout (dynamic) ----------------
#define ROWB 80            // 40 bf16 row stride in bytes
#define A_HI 0
#define A_LO 10240
#define B_HI 20480
#define B_LO 25600
#define BUFB 30720
#define DSMEM_BYTES (2 * BUFB)

// ---------------- kernel 1: ||e_c||^2 + sum(cluster_size) ----------------
__global__ void k_enorm(const float* __restrict__ embed,
                        const float* __restrict__ cluster_size) {
    if (blockIdx.x == 256) {
        __shared__ float red[128];
        int t = threadIdx.x;
        float s = 0.0f;
#pragma unroll
        for (int i = 0; i < 8; ++i) s += cluster_size[t + 128 * i];
        red[t] = s;
        __syncthreads();
#pragma unroll
        for (int o = 64; o > 0; o >>= 1) {
            if (t < o) red[t] += red[t + o];
            __syncthreads();
        }
        if (t == 0) g_cssum = red[0];
        return;
    }
    int w = threadIdx.x >> 5;
    int l = threadIdx.x & 31;
    int code = blockIdx.x * 4 + w;
    const float* row = embed + (size_t)code * DIM;
    float s = 0.0f;
#pragma unroll
    for (int i = 0; i < 8; ++i) {
        float v = row[l + 32 * i];
        s = fmaf(v, v, s);
    }
#pragma unroll
    for (int off = 16; off > 0; off >>= 1)
        s += __shfl_down_sync(0xffffffffu, s, off);
    if (l == 0) g_enorm[code] = s;
}

// ---------------- kernel 2: bf16x3 mma.sync GEMM + partial argmax ----------------
// R11 structure; single change: B fragments loaded via ldmatrix.x4 pairs
// (8 x2 -> 4 x4 issues per k16 step). Same values, same mma slots.
__global__ void __launch_bounds__(256, 2)
k_gemm_mma(const float* __restrict__ x, const float* __restrict__ embed) {
    extern __shared__ char smem[];
    uint32_t sb;
    asm("{ .reg .u64 t; cvta.to.shared.u64 t, %1; cvt.u32.u64 %0, t; }"
        : "=r"(sb) : "l"(smem));

    const int tid = threadIdx.x;
    const int wid = tid >> 5;
    const int lane = tid & 31;
    const int wm = wid & 3;      // token strip (32)
    const int wn = wid >> 2;     // code strip (32)
    const int blockTok = blockIdx.x * 128;
    const int cc = blockIdx.y;
    const int code0 = cc * 64;

    float acc[2][4][4];
#pragma unroll
    for (int t = 0; t < 2; ++t)
#pragma unroll
        for (int j = 0; j < 4; ++j)
#pragma unroll
            for (int r = 0; r < 4; ++r) acc[t][j][r] = 0.0f;

    const uint32_t arow = (uint32_t)((wm * 32 + (lane & 15)) * ROWB + (lane >> 4) * 16);
    // x4 B layout: lane groups 0-7/8-15 -> rows of n8-tile (2jj), k-halves;
    // lane groups 16-23/24-31 -> rows of n8-tile (2jj+1), k-halves.
    const uint32_t brow = (uint32_t)((wn * 32 + ((lane >> 4) & 1) * 8 + (lane & 7)) * ROWB
                                     + ((lane >> 3) & 1) * 16);

    float regA[16];
    float regB[8];

    // ---- prologue: load stage 0 ----
#pragma unroll
    for (int i = 0; i < 4; ++i) {
        int s_ = tid + i * 256;
        int row = s_ >> 3, ch = s_ & 7;
        *(float4*)(regA + i * 4) = *(const float4*)(x + (size_t)(blockTok + row) * DIM + ch * 4);
    }
#pragma unroll
    for (int i = 0; i < 2; ++i) {
        int s_ = tid + i * 256;
        int row = s_ >> 3, ch = s_ & 7;
        *(float4*)(regB + i * 4) = *(const float4*)(embed + (size_t)(code0 + row) * DIM + ch * 4);
    }

    for (int s = 0; s < 8; ++s) {
        const int b = s & 1;
        const char* bufw = smem + (b * BUFB);
        // store staged regs (stage s) into buffer b
#pragma unroll
        for (int i = 0; i < 4; ++i) {
            int s_ = tid + i * 256;
            int row = s_ >> 3, ch = s_ & 7;
            unsigned short h0, l0, h1, l1, h2, l2, h3, l3;
            bsplit(regA[i * 4 + 0], h0, l0);
            bsplit(regA[i * 4 + 1], h1, l1);
            bsplit(regA[i * 4 + 2], h2, l2);
            bsplit(regA[i * 4 + 3], h3, l3);
            uint2 hv = make_uint2((uint32_t)h0 | ((uint32_t)h1 << 16),
                                  (uint32_t)h2 | ((uint32_t)h3 << 16));
            uint2 lv = make_uint2((uint32_t)l0 | ((uint32_t)l1 << 16),
                                  (uint32_t)l2 | ((uint32_t)l3 << 16));
            *(uint2*)(bufw + A_HI + row * ROWB + ch * 8) = hv;
            *(uint2*)(bufw + A_LO + row * ROWB + ch * 8) = lv;
        }
#pragma unroll
        for (int i = 0; i < 2; ++i) {
            int s_ = tid + i * 256;
            int row = s_ >> 3, ch = s_ & 7;
            unsigned short h0, l0, h1, l1, h2, l2, h3, l3;
            bsplit(regB[i * 4 + 0], h0, l0);
            bsplit(regB[i * 4 + 1], h1, l1);
            bsplit(regB[i * 4 + 2], h2, l2);
            bsplit(regB[i * 4 + 3], h3, l3);
            uint2 hv = make_uint2((uint32_t)h0 | ((uint32_t)h1 << 16),
                                  (uint32_t)h2 | ((uint32_t)h3 << 16));
            uint2 lv = make_uint2((uint32_t)l0 | ((uint32_t)l1 << 16),
                                  (uint32_t)l2 | ((uint32_t)l3 << 16));
            *(uint2*)(bufw + B_HI + row * ROWB + ch * 8) = hv;
            *(uint2*)(bufw + B_LO + row * ROWB + ch * 8) = lv;
        }
        __syncthreads();

        // prefetch stage s+1 into regs (overlaps with mma below)
        if (s < 7) {
            const int kg = (s + 1) * 32;
#pragma unroll
            for (int i = 0; i < 4; ++i) {
                int s_ = tid + i * 256;
                int row = s_ >> 3, ch = s_ & 7;
                *(float4*)(regA + i * 4) = *(const float4*)(x + (size_t)(blockTok + row) * DIM + kg + ch * 4);
            }
#pragma unroll
            for (int i = 0; i < 2; ++i) {
                int s_ = tid + i * 256;
                int row = s_ >> 3, ch = s_ & 7;
                *(float4*)(regB + i * 4) = *(const float4*)(embed + (size_t)(code0 + row) * DIM + kg + ch * 4);
            }
        }

        // ---- compute on buffer b: 2 k16 steps, 3 split-products each ----
        const uint32_t base = sb + b * BUFB;
#pragma unroll
        for (int ks = 0; ks < 2; ++ks) {
            const uint32_t k0b = ks * 32;  // 16 bf16 = 32 bytes
            uint32_t af[2][4], bh[4][2], bl[4][2];
#pragma unroll
            for (int jj = 0; jj < 2; ++jj) {
                uint32_t r[4];
                ldsm_x4(r, base + B_HI + brow + jj * 16 * ROWB + k0b);
                bh[2 * jj][0] = r[0]; bh[2 * jj][1] = r[1];
                bh[2 * jj + 1][0] = r[2]; bh[2 * jj + 1][1] = r[3];
                ldsm_x4(r, base + B_LO + brow + jj * 16 * ROWB + k0b);
                bl[2 * jj][0] = r[0]; bl[2 * jj][1] = r[1];
                bl[2 * jj + 1][0] = r[2]; bl[2 * jj + 1][1] = r[3];
            }
#pragma unroll
            for (int t = 0; t < 2; ++t)
                ldsm_x4(af[t], base + A_HI + arow + t * 16 * ROWB + k0b);
#pragma unroll
            for (int t = 0; t < 2; ++t)
#pragma unroll
                for (int j = 0; j < 4; ++j) mma_bf16(acc[t][j], af[t], bh[j]);
#pragma unroll
            for (int t = 0; t < 2; ++t)
#pragma unroll
                for (int j = 0; j < 4; ++j) mma_bf16(acc[t][j], af[t], bl[j]);
#pragma unroll
            for (int t = 0; t < 2; ++t)
                ldsm_x4(af[t], base + A_LO + arow + t * 16 * ROWB + k0b);
#pragma unroll
            for (int t = 0; t < 2; ++t)
#pragma unroll
                for (int j = 0; j < 4; ++j) mma_bf16(acc[t][j], af[t], bh[j]);
        }
        // no end-of-stage sync needed (store(s+2) gated by sync(s+1))
    }

    // ---- epilogue: score + argmax ----
    const int g = lane >> 2;       // row within 8
    const int tg = lane & 3;       // col pair selector
    float best[4];
    int bidx[4];
#pragma unroll
    for (int r = 0; r < 4; ++r) { best[r] = -CUDART_INF_F; bidx[r] = 0x7fffffff; }

#pragma unroll
    for (int t = 0; t < 2; ++t) {
#pragma unroll
        for (int j = 0; j < 4; ++j) {
            int c0 = code0 + wn * 32 + j * 8 + tg * 2;
            float e0 = __ldg(&g_enorm[c0]);
            float e1 = __ldg(&g_enorm[c0 + 1]);
            float s00 = fmaf(2.0f, acc[t][j][0], -e0);
            float s01 = fmaf(2.0f, acc[t][j][1], -e1);
            float s10 = fmaf(2.0f, acc[t][j][2], -e0);
            float s11 = fmaf(2.0f, acc[t][j][3], -e1);
            int r0 = t * 2, r1 = t * 2 + 1;
            if (s00 > best[r0]) { best[r0] = s00; bidx[r0] = c0; }
            if (s01 > best[r0]) { best[r0] = s01; bidx[r0] = c0 + 1; }
            if (s10 > best[r1]) { best[r1] = s10; bidx[r1] = c0; }
            if (s11 > best[r1]) { best[r1] = s11; bidx[r1] = c0 + 1; }
        }
    }
#pragma unroll
    for (int r = 0; r < 4; ++r) {
#pragma unroll
        for (int off = 1; off < 4; off <<= 1) {
            float os = __shfl_xor_sync(0xffffffffu, best[r], off);
            int   oi = __shfl_xor_sync(0xffffffffu, bidx[r], off);
            if (os > best[r] || (os == best[r] && oi < bidx[r])) { best[r] = os; bidx[r] = oi; }
        }
    }

    __syncthreads();  // buffers done; reuse smem as reduce scratch
    float* red_s = (float*)smem;               // [128][2]
    int*   red_i = (int*)(smem + 1024);        // [128][2]
    if (tg == 0) {
#pragma unroll
        for (int r = 0; r < 4; ++r) {
            int t = r >> 1, rh = r & 1;
            int lrow = wm * 32 + t * 16 + rh * 8 + g;
            red_s[lrow * 2 + wn] = best[r];
            red_i[lrow * 2 + wn] = bidx[r];
        }
    }
    __syncthreads();
    if (tid < 128) {
        float s0 = red_s[tid * 2], s1 = red_s[tid * 2 + 1];
        int i0 = red_i[tid * 2], i1 = red_i[tid * 2 + 1];
        float bs = s0; int bb = i0;
        if (s1 > s0) { bs = s1; bb = i1; }   // strip 0 has lower codes: tie keeps 0
        int tok = blockTok + tid;
        g_pbest[cc * N_TOK + tok] = bs;
        g_pidx[cc * N_TOK + tok] = bb;
    }
}

// ---------------- kernel 3: fused cross-chunk argmax + gather quantize ----------------
__global__ void k_argmax_quant(const float* __restrict__ embed,
                               float* __restrict__ out_ind,
                               float* __restrict__ out_q) {
    int token = blockIdx.x * 8 + (threadIdx.x >> 5);
    int lane = threadIdx.x & 31;

    float bs = -CUDART_INF_F;
    int bi = 0x7fffffff;
    if (lane < NCHUNK) {
        bs = g_pbest[lane * N_TOK + token];
        bi = g_pidx[lane * N_TOK + token];
    }
#pragma unroll
    for (int off = 8; off > 0; off >>= 1) {
        float os = __shfl_down_sync(0xffffffffu, bs, off, 16);
        int   oi = __shfl_down_sync(0xffffffffu, bi, off, 16);
        if (os > bs || (os == bs && oi < bi)) { bs = os; bi = oi; }
    }
    bi = __shfl_sync(0xffffffffu, bi, 0);
    if (lane == 0) {
        g_idx[token] = bi;
        out_ind[token] = (float)bi;
    }
    const float4* er = (const float4*)(embed + (size_t)bi * DIM);
    float4* qw = (float4*)(out_q + (size_t)token * DIM);
    qw[lane] = er[lane];
    qw[lane + 32] = er[lane + 32];
}

// ---------------- kernel 4: multi-code segmented accumulation (R15-exact) ----------------
__global__ __launch_bounds__(256)
void k_accum(const float* __restrict__ x) {
    const int cg = blockIdx.x & 127;       // code group
    const int seg = blockIdx.x >> 7;       // segment
    const int c0 = cg * NCPB;
    const int tid = threadIdx.x;
    const int lane = tid & 31;
    const int w = tid >> 5;

    __shared__ int list[NCPB][256];
    __shared__ int wcnt[NCPB][8];
    __shared__ int wbase[NCPB][8];
    __shared__ int s_n[NCPB];

    float acc[NCPB];
    int total[NCPB];
#pragma unroll
    for (int q = 0; q < NCPB; ++q) { acc[q] = 0.0f; total[q] = 0; }

    const int tok0 = seg * SEG_TOK;
    for (int base = 0; base < SEG_TOK; base += 256) {
        int t = tok0 + base + tid;
        int rel = g_idx[t] - c0;           // 0..7 if one of ours
        unsigned myball = 0;
#pragma unroll
        for (int q = 0; q < NCPB; ++q) {
            unsigned ball = __ballot_sync(0xffffffffu, rel == q);
            if (lane == 0) wcnt[q][w] = __popc(ball);
            if (rel == q) myball = ball;
        }
        __syncthreads();
        if (tid < NCPB) {
            int s = 0;
#pragma unroll
            for (int i = 0; i < 8; ++i) { wbase[tid][i] = s; s += wcnt[tid][i]; }
            s_n[tid] = s;
        }
        __syncthreads();
        if ((unsigned)rel < (unsigned)NCPB) {
            int r = __popc(myball & ((1u << lane) - 1u));
            list[rel][wbase[rel][w] + r] = t;
        }
        __syncthreads();
#pragma unroll
        for (int q = 0; q < NCPB; ++q) {
            int n = s_n[q];
            for (int j = 0; j < n; ++j)
                acc[q] += x[(size_t)list[q][j] * DIM + tid];
            total[q] += n;
        }
        __syncthreads();
    }

#pragma unroll
    for (int q = 0; q < NCPB; ++q) {
        g_esum8[seg][(size_t)(c0 + q) * DIM + tid] = acc[q];
        if (tid == q) g_counts8[seg][c0 + q] = (float)total[q];
    }
}

// ---------------- kernel 5: fused EMA + Laplace smoothing + embed_norm ----------------
__global__ void k_fin(const float* __restrict__ cluster_size,
                      const float* __restrict__ embed_avg,
                      float* __restrict__ out_cs,
                      float* __restrict__ out_norm) {
    const int c = blockIdx.x;
    const int tid = threadIdx.x;

    float cnt = ((g_counts8[0][c] + g_counts8[1][c]) + (g_counts8[2][c] + g_counts8[3][c]))
              + ((g_counts8[4][c] + g_counts8[5][c]) + (g_counts8[6][c] + g_counts8[7][c]));
    float csn = DECAY * cluster_size[c] + ONE_M_DECAY * cnt;
    float n = DECAY * g_cssum + ONE_M_DECAY * (float)N_TOK;
    float denom = (csn + EPS) / (n + (float)NCODE * EPS) * n;
    float inv = 1.0f / denom;

    size_t i = (size_t)c * DIM + tid;
    float es = ((g_esum8[0][i] + g_esum8[1][i]) + (g_esum8[2][i] + g_esum8[3][i]))
             + ((g_esum8[4][i] + g_esum8[5][i]) + (g_esum8[6][i] + g_esum8[7][i]));
    float ea = DECAY * embed_avg[i] + ONE_M_DECAY * es;
    out_norm[i] = ea * inv;
    if (tid == 0) out_cs[c] = csn;
}

// ---------------- launch ----------------
extern "C" void kernel_launch(void* const* d_in, const int* in_sizes, int n_in,
                              void* d_out, int out_size) {
    const float* x = (const float*)d_in[0];
    const float* embed = (const float*)d_in[1];
    const float* embed_avg = (const float*)d_in[2];
    const float* cluster_size = (const float*)d_in[3];
    float* out = (float*)d_out;

    float* out_q    = out + OFF_Q;
    float* out_ind  = out + OFF_IND;
    float* out_norm = out + OFF_NORM;
    float* out_cs   = out + OFF_CS;

    cudaFuncSetAttribute(k_gemm_mma,
                         cudaFuncAttributeMaxDynamicSharedMemorySize,
                         DSMEM_BYTES);

    k_enorm<<<257, 128>>>(embed, cluster_size);
    dim3 g(N_TOK / 128, NCHUNK);
    k_gemm_mma<<<g, 256, DSMEM_BYTES>>>(x, embed);
    k_argmax_quant<<<N_TOK / 8, 256>>>(embed, out_ind, out_q);
    k_accum<<<128 * NSEG, 256>>>(x);
    k_fin<<<NCODE, 256>>>(cluster_size, embed_avg, out_cs, out_norm);
}